// round 14
// baseline (speedup 1.0000x reference)
#include <cuda_runtime.h>
#include <cuda_bf16.h>
#include <mma.h>
#include <cstdint>

using namespace nvcuda;

// GCN: out = Dr^{-1/2} A Ds^{-1/2} (X W + b)
// init -> degree -> scan(lookback) -> [role-split: GEMM blocks || fill blocks] -> gather
//   g[s]   = (sc_s[s]*x[s]) @ W          (GEMM, direct fragment store)
//   wsum[r]= sum_e sc_s[s_e]             (float atomic in fill role)
//   out[r] = sc_r * ( sum_e g[s_e] + wsum[r]*b )

#define MAX_N 100000
#define MAX_E 1600000
#define D 128
#define DV 32
#define SB 136            // bf16 smem row stride (elements)
#define TM 64             // rows per tile

#define GEMM_BLOCKS 264
#define TOTAL_BLOCKS 296   // 32 fill-only blocks

// smem: Wh 34816 | Wl 34816 | Xh 17408 | Xl 17408 = 104448
#define WH_OFF 0
#define WL_OFF 34816
#define XH_OFF 69632
#define XL_OFF 87040
#define SMEM_BYTES 104448

// ---- device scratch ----
__device__ float g_h[(size_t)(MAX_N + TM) * D];  // prescaled hidden (padded)
__device__ __nv_bfloat16 g_Wh[D * D];            // presplit W hi [k][n]
__device__ __nv_bfloat16 g_Wl[D * D];            // presplit W lo
__device__ float g_sc_s[MAX_N];
__device__ float g_sc_r[MAX_N];
__device__ float g_wsum[MAX_N];
__device__ int   g_deg_s[MAX_N];
__device__ int   g_deg_r[MAX_N];
__device__ int   g_row_start[MAX_N + 1];
__device__ int   g_row_cur[MAX_N];
__device__ int   g_edge_src[MAX_E];
__device__ unsigned long long g_state[256];      // lookback: (flag<<62)|value

// ---------------------------------------------------------------------------
__global__ void init_kernel(const float* __restrict__ W, int N, int nzero) {
    int t = threadIdx.x;
    int b = blockIdx.x;
    if (b < nzero) {
        int i = b * 256 + t;
        if (i < N) { g_deg_s[i] = 0; g_deg_r[i] = 0; g_wsum[i] = 0.f; }
        if (b == 0) g_state[t] = 0ull;
    } else {
        int idx = (b - nzero) * 256 + t;          // [0, 16384)
        float v = W[idx];
        __nv_bfloat16 h = __float2bfloat16(v);
        g_Wh[idx] = h;
        g_Wl[idx] = __float2bfloat16(v - __bfloat162float(h));
    }
}

__global__ void degree_kernel(const int* __restrict__ senders,
                              const int* __restrict__ receivers, int E) {
    int i = blockIdx.x * blockDim.x + threadIdx.x;
    int e = i * 4;
    if (e + 3 < E) {
        int4 s = *(const int4*)(senders + e);
        int4 r = *(const int4*)(receivers + e);
        atomicAdd(&g_deg_s[s.x], 1); atomicAdd(&g_deg_s[s.y], 1);
        atomicAdd(&g_deg_s[s.z], 1); atomicAdd(&g_deg_s[s.w], 1);
        atomicAdd(&g_deg_r[r.x], 1); atomicAdd(&g_deg_r[r.y], 1);
        atomicAdd(&g_deg_r[r.z], 1); atomicAdd(&g_deg_r[r.w], 1);
    } else {
        for (; e < E; e++) {
            atomicAdd(&g_deg_s[senders[e]], 1);
            atomicAdd(&g_deg_r[receivers[e]], 1);
        }
    }
}

// ---------------------------------------------------------------------------
__global__ __launch_bounds__(1024)
void scan_kernel(int N) {
    __shared__ int s[1024];
    __shared__ int ex_sh;
    int t = threadIdx.x;
    int b = blockIdx.x;
    int i = b * 1024 + t;
    int dr = (i < N) ? g_deg_r[i] : 0;
    s[t] = dr;
    __syncthreads();
    for (int off = 1; off < 1024; off <<= 1) {
        int tmp = (t >= off) ? s[t - off] : 0;
        __syncthreads();
        s[t] += tmp;
        __syncthreads();
    }
    int incl = s[t];
    int total = s[1023];

    if (t == 0) {
        if (b == 0) {
            atomicExch(&g_state[0], (2ull << 62) | (unsigned long long)total);
            ex_sh = 0;
        } else {
            atomicExch(&g_state[b], (1ull << 62) | (unsigned long long)total);
            long long ex = 0;
            int p = b - 1;
            while (true) {
                unsigned long long st;
                do { st = atomicAdd(&g_state[p], 0ull); } while ((st >> 62) == 0);
                ex += (long long)(st & 0x3FFFFFFFFFFFFFFFull);
                if ((st >> 62) == 2ull) break;
                p--;
            }
            atomicExch(&g_state[b],
                       (2ull << 62) | (unsigned long long)(ex + total));
            ex_sh = (int)ex;
        }
    }
    __syncthreads();
    int base = ex_sh;

    if (i < N) {
        int start = base + incl - dr;
        g_row_start[i] = start;
        g_row_cur[i]   = start;
        g_sc_r[i] = rsqrtf((float)max(dr, 1));
        g_sc_s[i] = rsqrtf((float)max(g_deg_s[i], 1));
        if (i == N - 1) g_row_start[N] = base + incl;
    }
}

// ---------------------------------------------------------------------------
__device__ __forceinline__ void split_store(__nv_bfloat16* hi, __nv_bfloat16* lo,
                                            int idx, float v) {
    __nv_bfloat16 h = __float2bfloat16(v);
    float r = v - __bfloat162float(h);
    hi[idx] = h;
    lo[idx] = __float2bfloat16(r);
}

// Role-split launch: blocks [0,GEMM_BLOCKS) run the persistent bf16x3 wmma GEMM
// (64-row tiles, W staged once, X prescaled by sc_s, direct fragment store);
// blocks [GEMM_BLOCKS,TOTAL_BLOCKS) run the CSR fill + wsum concurrently.
__global__ __launch_bounds__(256, 2)
void gemmfill_kernel(const float* __restrict__ x,
                     const int* __restrict__ senders,
                     const int* __restrict__ receivers,
                     int N, int E, int nT) {
    int t = threadIdx.x;

    if (blockIdx.x >= GEMM_BLOCKS) {
        // ---------------- fill role ----------------
        int fb = blockIdx.x - GEMM_BLOCKS;
        const int nFill = TOTAL_BLOCKS - GEMM_BLOCKS;
        int gid = fb * 256 + t;
        int stride = nFill * 256;
        for (int e = gid; e < E; e += stride) {
            int r0 = receivers[e], s0 = senders[e];
            int pos = atomicAdd(&g_row_cur[r0], 1);
            g_edge_src[pos] = s0;
            atomicAdd(&g_wsum[r0], g_sc_s[s0]);
        }
        return;
    }

    // ---------------- GEMM role ----------------
    extern __shared__ char sm[];
    __nv_bfloat16* Wh = (__nv_bfloat16*)(sm + WH_OFF);
    __nv_bfloat16* Wl = (__nv_bfloat16*)(sm + WL_OFF);
    __nv_bfloat16* Xh = (__nv_bfloat16*)(sm + XH_OFF);
    __nv_bfloat16* Xl = (__nv_bfloat16*)(sm + XL_OFF);

    int w = t >> 5;
    int wr = w >> 1, wc = w & 1;   // warp tile: rows [wr*16,+16), cols [wc*64,+64)

    // stage presplit W once per block
    {
        const uint4* WhG = (const uint4*)g_Wh;
        const uint4* WlG = (const uint4*)g_Wl;
        for (int i = t; i < D * 16; i += 256) {
            int row = i >> 4, c8 = (i & 15) * 8;
            int o = row * SB + c8;
            *(uint4*)(Wh + o) = WhG[i];
            *(uint4*)(Wl + o) = WlG[i];
        }
    }

    const float4* Xv = (const float4*)x;

    bool first = true;
    for (int tile = blockIdx.x; tile < nT; tile += GEMM_BLOCKS) {
        int rowTile = tile * TM;
        if (!first) __syncthreads();   // protect Xh/Xl from previous readers
        first = false;

        // stage X tile [TM x 128], rows prescaled by sc_s, hi/lo split
        for (int i = t; i < TM * DV; i += 256) {
            int row = i >> 5, c = (i & 31) * 4;
            int gr = rowTile + row;
            float4 v = make_float4(0.f, 0.f, 0.f, 0.f);
            float scs = 0.f;
            if (gr < N) {
                v = Xv[(size_t)gr * DV + (i & 31)];
                scs = g_sc_s[gr];
            }
            int b0 = row * SB + c;
            split_store(Xh, Xl, b0 + 0, v.x * scs);
            split_store(Xh, Xl, b0 + 1, v.y * scs);
            split_store(Xh, Xl, b0 + 2, v.z * scs);
            split_store(Xh, Xl, b0 + 3, v.w * scs);
        }
        __syncthreads();

        wmma::fragment<wmma::accumulator, 16, 16, 16, float> acc[4];
#pragma unroll
        for (int nt = 0; nt < 4; nt++) wmma::fill_fragment(acc[nt], 0.0f);

#pragma unroll
        for (int ks = 0; ks < 8; ks++) {
            wmma::fragment<wmma::matrix_a, 16, 16, 16, __nv_bfloat16, wmma::row_major> ah, al;
            wmma::load_matrix_sync(ah, Xh + (wr * 16) * SB + ks * 16, SB);
            wmma::load_matrix_sync(al, Xl + (wr * 16) * SB + ks * 16, SB);
#pragma unroll
            for (int nt = 0; nt < 4; nt++) {
                int col = wc * 64 + nt * 16;
                wmma::fragment<wmma::matrix_b, 16, 16, 16, __nv_bfloat16, wmma::row_major> bh, bl;
                wmma::load_matrix_sync(bh, Wh + (ks * 16) * SB + col, SB);
                wmma::load_matrix_sync(bl, Wl + (ks * 16) * SB + col, SB);
                wmma::mma_sync(acc[nt], ah, bh, acc[nt]);
                wmma::mma_sync(acc[nt], ah, bl, acc[nt]);
                wmma::mma_sync(acc[nt], al, bh, acc[nt]);
            }
        }

        // direct store to g_h (padded, last tile safe)
#pragma unroll
        for (int nt = 0; nt < 4; nt++)
            wmma::store_matrix_sync(
                g_h + (size_t)(rowTile + wr * 16) * D + wc * 64 + nt * 16,
                acc[nt], D, wmma::mem_row_major);
    }
}

// ---------------------------------------------------------------------------
// One warp per receiver; plain sums (h prescaled); out = sc_r*(acc + wsum*b).
__global__ __launch_bounds__(256)
void agg_kernel(float* __restrict__ out, const float* __restrict__ bias, int N) {
    int wg = (blockIdx.x * blockDim.x + threadIdx.x) >> 5;
    int lane = threadIdx.x & 31;
    if (wg >= N) return;

    int beg = g_row_start[wg];
    int end = g_row_start[wg + 1];

    const float4* __restrict__ h4 = (const float4*)g_h;
    float4 acc0 = make_float4(0.f, 0.f, 0.f, 0.f);
    float4 acc1 = make_float4(0.f, 0.f, 0.f, 0.f);
    int e = beg;
    for (; e + 7 < end; e += 8) {
        int s0 = g_edge_src[e],     s1 = g_edge_src[e + 1];
        int s2 = g_edge_src[e + 2], s3 = g_edge_src[e + 3];
        int s4 = g_edge_src[e + 4], s5 = g_edge_src[e + 5];
        int s6 = g_edge_src[e + 6], s7 = g_edge_src[e + 7];
        float4 a0 = h4[(size_t)s0 * DV + lane];
        float4 a1 = h4[(size_t)s1 * DV + lane];
        float4 a2 = h4[(size_t)s2 * DV + lane];
        float4 a3 = h4[(size_t)s3 * DV + lane];
        float4 a4 = h4[(size_t)s4 * DV + lane];
        float4 a5 = h4[(size_t)s5 * DV + lane];
        float4 a6 = h4[(size_t)s6 * DV + lane];
        float4 a7 = h4[(size_t)s7 * DV + lane];
        acc0.x += (a0.x + a1.x) + (a2.x + a3.x);
        acc0.y += (a0.y + a1.y) + (a2.y + a3.y);
        acc0.z += (a0.z + a1.z) + (a2.z + a3.z);
        acc0.w += (a0.w + a1.w) + (a2.w + a3.w);
        acc1.x += (a4.x + a5.x) + (a6.x + a7.x);
        acc1.y += (a4.y + a5.y) + (a6.y + a7.y);
        acc1.z += (a4.z + a5.z) + (a6.z + a7.z);
        acc1.w += (a4.w + a5.w) + (a6.w + a7.w);
    }
    for (; e < end; e++) {
        int s0 = g_edge_src[e];
        float4 a0 = h4[(size_t)s0 * DV + lane];
        acc0.x += a0.x; acc0.y += a0.y; acc0.z += a0.z; acc0.w += a0.w;
    }

    float sc = g_sc_r[wg];
    float ws = g_wsum[wg];
    float4 bv = ((const float4*)bias)[lane];
    float4 o;
    o.x = (acc0.x + acc1.x + ws * bv.x) * sc;
    o.y = (acc0.y + acc1.y + ws * bv.y) * sc;
    o.z = (acc0.z + acc1.z + ws * bv.z) * sc;
    o.w = (acc0.w + acc1.w + ws * bv.w) * sc;
    ((float4*)out)[(size_t)wg * DV + lane] = o;
}

// ---------------------------------------------------------------------------
extern "C" void kernel_launch(void* const* d_in, const int* in_sizes, int n_in,
                              void* d_out, int out_size) {
    const float* x         = (const float*)d_in[0];
    const int*   senders   = (const int*)d_in[1];
    const int*   receivers = (const int*)d_in[2];
    const float* W    = (const float*)d_in[n_in - 2];
    const float* bias = (const float*)d_in[n_in - 1];

    int N = in_sizes[0] / D;
    int E = in_sizes[1];

    static bool attr_set = false;
    if (!attr_set) {
        cudaFuncSetAttribute(gemmfill_kernel,
                             cudaFuncAttributeMaxDynamicSharedMemorySize,
                             SMEM_BYTES);
        attr_set = true;
    }

    int nzero = (N + 255) / 256;
    int nSB   = (N + 1023) / 1024;
    int nT    = (N + TM - 1) / TM;
    int nE4   = (E / 4 + 255) / 256 + 1;

    init_kernel   <<<nzero + (D * D) / 256, 256>>>(W, N, nzero);
    degree_kernel <<<nE4, 256>>>(senders, receivers, E);
    scan_kernel   <<<nSB, 1024>>>(N);
    gemmfill_kernel<<<TOTAL_BLOCKS, 256, SMEM_BYTES>>>(x, senders, receivers, N, E, nT);
    agg_kernel    <<<(N * 32 + 255) / 256, 256>>>((float*)d_out, bias, N);
}

// round 15
// speedup vs baseline: 1.5960x; 1.5960x over previous
#include <cuda_runtime.h>
#include <cuda_bf16.h>
#include <mma.h>
#include <cstdint>

using namespace nvcuda;

// GCN: out = Dr^{-1/2} A Ds^{-1/2} (X W + b)
// [degree+Wsplit] -> scan(lookback) -> [persistent wmma GEMM + fill(+wsum)] -> gather(+cleanup)
// Device globals start zero-initialized; agg re-zeros deg/wsum/state for the
// next graph replay, so no init launch is needed.

#define MAX_N 100000
#define MAX_E 1600000
#define D 128
#define DV 32
#define SB 136            // bf16 smem row stride (elements)
#define TM 64             // rows per tile

// smem: Wh 34816 | Wl 34816 | Xh 17408 | Xl 17408 = 104448
#define WH_OFF 0
#define WL_OFF 34816
#define XH_OFF 69632
#define XL_OFF 87040
#define SMEM_BYTES 104448

// ---- device scratch (zero-initialized at load) ----
__device__ float g_h[(size_t)(MAX_N + TM) * D];  // prescaled hidden (padded)
__device__ __nv_bfloat16 g_Wh[D * D];            // presplit W hi [k][n]
__device__ __nv_bfloat16 g_Wl[D * D];            // presplit W lo
__device__ float g_sc_s[MAX_N];
__device__ float g_sc_r[MAX_N];
__device__ float g_wsum[MAX_N];
__device__ int   g_deg_s[MAX_N];
__device__ int   g_deg_r[MAX_N];
__device__ int   g_row_start[MAX_N + 1];
__device__ int   g_row_cur[MAX_N];
__device__ int   g_edge_src[MAX_E];
__device__ unsigned long long g_state[256];      // lookback: (flag<<62)|value

// ---------------------------------------------------------------------------
// degree histogram (blocks < nE4) + W hi/lo split (blocks >= nE4)
__global__ void degW_kernel(const int* __restrict__ senders,
                            const int* __restrict__ receivers,
                            const float* __restrict__ W, int E, int nE4) {
    int t = threadIdx.x;
    int b = blockIdx.x;
    if (b >= nE4) {
        int idx = (b - nE4) * 256 + t;            // [0, 16384)
        float v = W[idx];
        __nv_bfloat16 h = __float2bfloat16(v);
        g_Wh[idx] = h;
        g_Wl[idx] = __float2bfloat16(v - __bfloat162float(h));
        return;
    }
    int i = b * 256 + t;
    int e = i * 4;
    if (e + 3 < E) {
        int4 s = *(const int4*)(senders + e);
        int4 r = *(const int4*)(receivers + e);
        atomicAdd(&g_deg_s[s.x], 1); atomicAdd(&g_deg_s[s.y], 1);
        atomicAdd(&g_deg_s[s.z], 1); atomicAdd(&g_deg_s[s.w], 1);
        atomicAdd(&g_deg_r[r.x], 1); atomicAdd(&g_deg_r[r.y], 1);
        atomicAdd(&g_deg_r[r.z], 1); atomicAdd(&g_deg_r[r.w], 1);
    } else {
        for (; e < E; e++) {
            atomicAdd(&g_deg_s[senders[e]], 1);
            atomicAdd(&g_deg_r[receivers[e]], 1);
        }
    }
}

// ---------------------------------------------------------------------------
__global__ __launch_bounds__(1024)
void scan_kernel(int N) {
    __shared__ int s[1024];
    __shared__ int ex_sh;
    int t = threadIdx.x;
    int b = blockIdx.x;
    int i = b * 1024 + t;
    int dr = (i < N) ? g_deg_r[i] : 0;
    s[t] = dr;
    __syncthreads();
    for (int off = 1; off < 1024; off <<= 1) {
        int tmp = (t >= off) ? s[t - off] : 0;
        __syncthreads();
        s[t] += tmp;
        __syncthreads();
    }
    int incl = s[t];
    int total = s[1023];

    if (t == 0) {
        if (b == 0) {
            atomicExch(&g_state[0], (2ull << 62) | (unsigned long long)total);
            ex_sh = 0;
        } else {
            atomicExch(&g_state[b], (1ull << 62) | (unsigned long long)total);
            long long ex = 0;
            int p = b - 1;
            while (true) {
                unsigned long long st;
                do { st = atomicAdd(&g_state[p], 0ull); } while ((st >> 62) == 0);
                ex += (long long)(st & 0x3FFFFFFFFFFFFFFFull);
                if ((st >> 62) == 2ull) break;
                p--;
            }
            atomicExch(&g_state[b],
                       (2ull << 62) | (unsigned long long)(ex + total));
            ex_sh = (int)ex;
        }
    }
    __syncthreads();
    int base = ex_sh;

    if (i < N) {
        int start = base + incl - dr;
        g_row_start[i] = start;
        g_row_cur[i]   = start;
        g_sc_r[i] = rsqrtf((float)max(dr, 1));
        g_sc_s[i] = rsqrtf((float)max(g_deg_s[i], 1));
        if (i == N - 1) g_row_start[N] = base + incl;
    }
}

// ---------------------------------------------------------------------------
__device__ __forceinline__ void split_store(__nv_bfloat16* hi, __nv_bfloat16* lo,
                                            int idx, float v) {
    __nv_bfloat16 h = __float2bfloat16(v);
    float r = v - __bfloat162float(h);
    hi[idx] = h;
    lo[idx] = __float2bfloat16(r);
}

// Persistent bf16x3 wmma GEMM, 64-row tiles, W staged once per block,
// X prescaled by sc_s, direct fragment store. Then grid-strided fill+wsum.
__global__ __launch_bounds__(256, 2)
void gemmfill_kernel(const float* __restrict__ x,
                     const int* __restrict__ senders,
                     const int* __restrict__ receivers,
                     int N, int E, int nT) {
    extern __shared__ char sm[];
    __nv_bfloat16* Wh = (__nv_bfloat16*)(sm + WH_OFF);
    __nv_bfloat16* Wl = (__nv_bfloat16*)(sm + WL_OFF);
    __nv_bfloat16* Xh = (__nv_bfloat16*)(sm + XH_OFF);
    __nv_bfloat16* Xl = (__nv_bfloat16*)(sm + XL_OFF);

    int t = threadIdx.x;
    int w = t >> 5;
    int wr = w >> 1, wc = w & 1;   // warp tile: rows [wr*16,+16), cols [wc*64,+64)

    // stage presplit W once per block
    {
        const uint4* WhG = (const uint4*)g_Wh;
        const uint4* WlG = (const uint4*)g_Wl;
        for (int i = t; i < D * 16; i += 256) {
            int row = i >> 4, c8 = (i & 15) * 8;
            int o = row * SB + c8;
            *(uint4*)(Wh + o) = WhG[i];
            *(uint4*)(Wl + o) = WlG[i];
        }
    }

    const float4* Xv = (const float4*)x;

    bool first = true;
    for (int tile = blockIdx.x; tile < nT; tile += gridDim.x) {
        int rowTile = tile * TM;
        if (!first) __syncthreads();   // protect Xh/Xl from previous readers
        first = false;

        // stage X tile [TM x 128], rows prescaled by sc_s, hi/lo split
        for (int i = t; i < TM * DV; i += 256) {
            int row = i >> 5, c = (i & 31) * 4;
            int gr = rowTile + row;
            float4 v = make_float4(0.f, 0.f, 0.f, 0.f);
            float scs = 0.f;
            if (gr < N) {
                v = Xv[(size_t)gr * DV + (i & 31)];
                scs = g_sc_s[gr];
            }
            int b0 = row * SB + c;
            split_store(Xh, Xl, b0 + 0, v.x * scs);
            split_store(Xh, Xl, b0 + 1, v.y * scs);
            split_store(Xh, Xl, b0 + 2, v.z * scs);
            split_store(Xh, Xl, b0 + 3, v.w * scs);
        }
        __syncthreads();

        wmma::fragment<wmma::accumulator, 16, 16, 16, float> acc[4];
#pragma unroll
        for (int nt = 0; nt < 4; nt++) wmma::fill_fragment(acc[nt], 0.0f);

#pragma unroll
        for (int ks = 0; ks < 8; ks++) {
            wmma::fragment<wmma::matrix_a, 16, 16, 16, __nv_bfloat16, wmma::row_major> ah, al;
            wmma::load_matrix_sync(ah, Xh + (wr * 16) * SB + ks * 16, SB);
            wmma::load_matrix_sync(al, Xl + (wr * 16) * SB + ks * 16, SB);
#pragma unroll
            for (int nt = 0; nt < 4; nt++) {
                int col = wc * 64 + nt * 16;
                wmma::fragment<wmma::matrix_b, 16, 16, 16, __nv_bfloat16, wmma::row_major> bh, bl;
                wmma::load_matrix_sync(bh, Wh + (ks * 16) * SB + col, SB);
                wmma::load_matrix_sync(bl, Wl + (ks * 16) * SB + col, SB);
                wmma::mma_sync(acc[nt], ah, bh, acc[nt]);
                wmma::mma_sync(acc[nt], ah, bl, acc[nt]);
                wmma::mma_sync(acc[nt], al, bh, acc[nt]);
            }
        }

        // direct store to g_h (padded, last tile safe)
#pragma unroll
        for (int nt = 0; nt < 4; nt++)
            wmma::store_matrix_sync(
                g_h + (size_t)(rowTile + wr * 16) * D + wc * 64 + nt * 16,
                acc[nt], D, wmma::mem_row_major);
    }

    // ---------------- fill phase (grid-strided), also accumulates wsum ----
    int gid = blockIdx.x * 256 + t;
    int stride = gridDim.x * 256;
    int e = gid;
    for (; e + stride < E; e += 2 * stride) {
        int r0 = receivers[e], r1 = receivers[e + stride];
        int s0 = senders[e],   s1 = senders[e + stride];
        int p0 = atomicAdd(&g_row_cur[r0], 1);
        int p1 = atomicAdd(&g_row_cur[r1], 1);
        g_edge_src[p0] = s0;
        g_edge_src[p1] = s1;
        atomicAdd(&g_wsum[r0], g_sc_s[s0]);
        atomicAdd(&g_wsum[r1], g_sc_s[s1]);
    }
    if (e < E) {
        int r0 = receivers[e], s0 = senders[e];
        int pos = atomicAdd(&g_row_cur[r0], 1);
        g_edge_src[pos] = s0;
        atomicAdd(&g_wsum[r0], g_sc_s[s0]);
    }
}

// ---------------------------------------------------------------------------
// One warp per receiver; plain sums (h prescaled); out = sc_r*(acc + wsum*b).
// Tail: reset deg/wsum/state so the next graph replay starts clean.
__global__ __launch_bounds__(256)
void agg_kernel(float* __restrict__ out, const float* __restrict__ bias, int N) {
    int wg = (blockIdx.x * blockDim.x + threadIdx.x) >> 5;
    int lane = threadIdx.x & 31;

    // reset lookback state for next replay (independent of node work)
    if (blockIdx.x == 0 && threadIdx.x < 256) g_state[threadIdx.x] = 0ull;

    if (wg >= N) return;

    int beg = g_row_start[wg];
    int end = g_row_start[wg + 1];

    const float4* __restrict__ h4 = (const float4*)g_h;
    float4 acc0 = make_float4(0.f, 0.f, 0.f, 0.f);
    float4 acc1 = make_float4(0.f, 0.f, 0.f, 0.f);
    int e = beg;
    for (; e + 7 < end; e += 8) {
        int s0 = g_edge_src[e],     s1 = g_edge_src[e + 1];
        int s2 = g_edge_src[e + 2], s3 = g_edge_src[e + 3];
        int s4 = g_edge_src[e + 4], s5 = g_edge_src[e + 5];
        int s6 = g_edge_src[e + 6], s7 = g_edge_src[e + 7];
        float4 a0 = h4[(size_t)s0 * DV + lane];
        float4 a1 = h4[(size_t)s1 * DV + lane];
        float4 a2 = h4[(size_t)s2 * DV + lane];
        float4 a3 = h4[(size_t)s3 * DV + lane];
        float4 a4 = h4[(size_t)s4 * DV + lane];
        float4 a5 = h4[(size_t)s5 * DV + lane];
        float4 a6 = h4[(size_t)s6 * DV + lane];
        float4 a7 = h4[(size_t)s7 * DV + lane];
        acc0.x += (a0.x + a1.x) + (a2.x + a3.x);
        acc0.y += (a0.y + a1.y) + (a2.y + a3.y);
        acc0.z += (a0.z + a1.z) + (a2.z + a3.z);
        acc0.w += (a0.w + a1.w) + (a2.w + a3.w);
        acc1.x += (a4.x + a5.x) + (a6.x + a7.x);
        acc1.y += (a4.y + a5.y) + (a6.y + a7.y);
        acc1.z += (a4.z + a5.z) + (a6.z + a7.z);
        acc1.w += (a4.w + a5.w) + (a6.w + a7.w);
    }
    for (; e < end; e++) {
        int s0 = g_edge_src[e];
        float4 a0 = h4[(size_t)s0 * DV + lane];
        acc0.x += a0.x; acc0.y += a0.y; acc0.z += a0.z; acc0.w += a0.w;
    }

    float sc = g_sc_r[wg];
    float ws = g_wsum[wg];
    float4 bv = ((const float4*)bias)[lane];
    float4 o;
    o.x = (acc0.x + acc1.x + ws * bv.x) * sc;
    o.y = (acc0.y + acc1.y + ws * bv.y) * sc;
    o.z = (acc0.z + acc1.z + ws * bv.z) * sc;
    o.w = (acc0.w + acc1.w + ws * bv.w) * sc;
    ((float4*)out)[(size_t)wg * DV + lane] = o;

    // cleanup for next replay: all lanes have consumed wsum; sync then reset
    __syncwarp();
    if (lane == 0) {
        g_wsum[wg]  = 0.f;
        g_deg_s[wg] = 0;
        g_deg_r[wg] = 0;
    }
}

// ---------------------------------------------------------------------------
extern "C" void kernel_launch(void* const* d_in, const int* in_sizes, int n_in,
                              void* d_out, int out_size) {
    const float* x         = (const float*)d_in[0];
    const int*   senders   = (const int*)d_in[1];
    const int*   receivers = (const int*)d_in[2];
    const float* W    = (const float*)d_in[n_in - 2];
    const float* bias = (const float*)d_in[n_in - 1];

    int N = in_sizes[0] / D;
    int E = in_sizes[1];

    static bool attr_set = false;
    if (!attr_set) {
        cudaFuncSetAttribute(gemmfill_kernel,
                             cudaFuncAttributeMaxDynamicSharedMemorySize,
                             SMEM_BYTES);
        attr_set = true;
    }

    int nSB = (N + 1023) / 1024;
    int nT  = (N + TM - 1) / TM;
    int nE4 = (E / 4 + 255) / 256 + 1;

    degW_kernel   <<<nE4 + (D * D) / 256, 256>>>(senders, receivers, W, E, nE4);
    scan_kernel   <<<nSB, 1024>>>(N);
    gemmfill_kernel<<<296, 256, SMEM_BYTES>>>(x, senders, receivers, N, E, nT);
    agg_kernel    <<<(N * 32 + 255) / 256, 256>>>((float*)d_out, bias, N);
}

// round 16
// speedup vs baseline: 1.6722x; 1.0477x over previous
#include <cuda_runtime.h>
#include <cuda_bf16.h>
#include <mma.h>
#include <cstdint>

using namespace nvcuda;

// GCN: out = Dr^{-1/2} A Ds^{-1/2} (X W + b)
// init -> degree -> scan(lookback) -> [persistent wmma GEMM + fill(+wsum)] -> gather
//   g[s]   = (sc_s[s]*x[s]) @ W          (GEMM, direct fragment store)
//   wsum[r]= sum_e sc_s[s_e]             (float atomic in fill)
//   out[r] = sc_r * ( sum_e g[s_e] + wsum[r]*b )

#define MAX_N 100000
#define MAX_E 1600000
#define D 128
#define DV 32
#define SB 136            // bf16 smem row stride (elements)
#define TM 64             // rows per tile

// smem: Wh 34816 | Wl 34816 | Xh 17408 | Xl 17408 = 104448
#define WH_OFF 0
#define WL_OFF 34816
#define XH_OFF 69632
#define XL_OFF 87040
#define SMEM_BYTES 104448

// ---- device scratch ----
__device__ float g_h[(size_t)(MAX_N + TM) * D];  // prescaled hidden (padded)
__device__ __nv_bfloat16 g_Wh[D * D];            // presplit W hi [k][n]
__device__ __nv_bfloat16 g_Wl[D * D];            // presplit W lo
__device__ float g_sc_s[MAX_N];
__device__ float g_sc_r[MAX_N];
__device__ float g_wsum[MAX_N];
__device__ int   g_deg_s[MAX_N];
__device__ int   g_deg_r[MAX_N];
__device__ int   g_row_start[MAX_N + 1];
__device__ int   g_row_cur[MAX_N];
__device__ int   g_edge_src[MAX_E];
__device__ unsigned long long g_state[256];      // lookback: (flag<<62)|value

// ---------------------------------------------------------------------------
__global__ void init_kernel(const float* __restrict__ W, int N, int nzero) {
    int t = threadIdx.x;
    int b = blockIdx.x;
    if (b < nzero) {
        int i = b * 256 + t;
        if (i < N) { g_deg_s[i] = 0; g_deg_r[i] = 0; g_wsum[i] = 0.f; }
        if (b == 0) g_state[t] = 0ull;
    } else {
        int idx = (b - nzero) * 256 + t;          // [0, 16384)
        float v = W[idx];
        __nv_bfloat16 h = __float2bfloat16(v);
        g_Wh[idx] = h;
        g_Wl[idx] = __float2bfloat16(v - __bfloat162float(h));
    }
}

__global__ void degree_kernel(const int* __restrict__ senders,
                              const int* __restrict__ receivers, int E) {
    int i = blockIdx.x * blockDim.x + threadIdx.x;
    int e = i * 4;
    if (e + 3 < E) {
        int4 s = *(const int4*)(senders + e);
        int4 r = *(const int4*)(receivers + e);
        atomicAdd(&g_deg_s[s.x], 1); atomicAdd(&g_deg_s[s.y], 1);
        atomicAdd(&g_deg_s[s.z], 1); atomicAdd(&g_deg_s[s.w], 1);
        atomicAdd(&g_deg_r[r.x], 1); atomicAdd(&g_deg_r[r.y], 1);
        atomicAdd(&g_deg_r[r.z], 1); atomicAdd(&g_deg_r[r.w], 1);
    } else {
        for (; e < E; e++) {
            atomicAdd(&g_deg_s[senders[e]], 1);
            atomicAdd(&g_deg_r[receivers[e]], 1);
        }
    }
}

// ---------------------------------------------------------------------------
__global__ __launch_bounds__(1024)
void scan_kernel(int N) {
    __shared__ int s[1024];
    __shared__ int ex_sh;
    int t = threadIdx.x;
    int b = blockIdx.x;
    int i = b * 1024 + t;
    int dr = (i < N) ? g_deg_r[i] : 0;
    s[t] = dr;
    __syncthreads();
    for (int off = 1; off < 1024; off <<= 1) {
        int tmp = (t >= off) ? s[t - off] : 0;
        __syncthreads();
        s[t] += tmp;
        __syncthreads();
    }
    int incl = s[t];
    int total = s[1023];

    if (t == 0) {
        if (b == 0) {
            atomicExch(&g_state[0], (2ull << 62) | (unsigned long long)total);
            ex_sh = 0;
        } else {
            atomicExch(&g_state[b], (1ull << 62) | (unsigned long long)total);
            long long ex = 0;
            int p = b - 1;
            while (true) {
                unsigned long long st;
                do { st = atomicAdd(&g_state[p], 0ull); } while ((st >> 62) == 0);
                ex += (long long)(st & 0x3FFFFFFFFFFFFFFFull);
                if ((st >> 62) == 2ull) break;
                p--;
            }
            atomicExch(&g_state[b],
                       (2ull << 62) | (unsigned long long)(ex + total));
            ex_sh = (int)ex;
        }
    }
    __syncthreads();
    int base = ex_sh;

    if (i < N) {
        int start = base + incl - dr;
        g_row_start[i] = start;
        g_row_cur[i]   = start;
        g_sc_r[i] = rsqrtf((float)max(dr, 1));
        g_sc_s[i] = rsqrtf((float)max(g_deg_s[i], 1));
        if (i == N - 1) g_row_start[N] = base + incl;
    }
}

// ---------------------------------------------------------------------------
// Packed hi/lo split of a float4 -> one 8B store to each of hi/lo.
__device__ __forceinline__ void split_store4(__nv_bfloat16* hi, __nv_bfloat16* lo,
                                             int idx, float4 v) {
    __nv_bfloat162 h01 = __floats2bfloat162_rn(v.x, v.y);
    __nv_bfloat162 h23 = __floats2bfloat162_rn(v.z, v.w);
    float lx = v.x - __bfloat162float(__low2bfloat16(h01));
    float ly = v.y - __bfloat162float(__high2bfloat16(h01));
    float lz = v.z - __bfloat162float(__low2bfloat16(h23));
    float lw = v.w - __bfloat162float(__high2bfloat16(h23));
    __nv_bfloat162 l01 = __floats2bfloat162_rn(lx, ly);
    __nv_bfloat162 l23 = __floats2bfloat162_rn(lz, lw);
    uint2 hp, lp;
    hp.x = *reinterpret_cast<uint32_t*>(&h01);
    hp.y = *reinterpret_cast<uint32_t*>(&h23);
    lp.x = *reinterpret_cast<uint32_t*>(&l01);
    lp.y = *reinterpret_cast<uint32_t*>(&l23);
    *reinterpret_cast<uint2*>(hi + idx) = hp;
    *reinterpret_cast<uint2*>(lo + idx) = lp;
}

// Persistent bf16x3 wmma GEMM, 64-row tiles, W staged once per block,
// X prescaled by sc_s, direct fragment store. Then grid-strided fill+wsum.
__global__ __launch_bounds__(256, 2)
void gemmfill_kernel(const float* __restrict__ x,
                     const int* __restrict__ senders,
                     const int* __restrict__ receivers,
                     int N, int E, int nT) {
    extern __shared__ char sm[];
    __nv_bfloat16* Wh = (__nv_bfloat16*)(sm + WH_OFF);
    __nv_bfloat16* Wl = (__nv_bfloat16*)(sm + WL_OFF);
    __nv_bfloat16* Xh = (__nv_bfloat16*)(sm + XH_OFF);
    __nv_bfloat16* Xl = (__nv_bfloat16*)(sm + XL_OFF);

    int t = threadIdx.x;
    int w = t >> 5;
    int wr = w >> 1, wc = w & 1;   // warp tile: rows [wr*16,+16), cols [wc*64,+64)

    // stage presplit W once per block
    {
        const uint4* WhG = (const uint4*)g_Wh;
        const uint4* WlG = (const uint4*)g_Wl;
        for (int i = t; i < D * 16; i += 256) {
            int row = i >> 4, c8 = (i & 15) * 8;
            int o = row * SB + c8;
            *(uint4*)(Wh + o) = WhG[i];
            *(uint4*)(Wl + o) = WlG[i];
        }
    }

    const float4* Xv = (const float4*)x;

    bool first = true;
    for (int tile = blockIdx.x; tile < nT; tile += gridDim.x) {
        int rowTile = tile * TM;
        if (!first) __syncthreads();   // protect Xh/Xl from previous readers
        first = false;

        // stage X tile [TM x 128], rows prescaled by sc_s, packed hi/lo split
        for (int i = t; i < TM * DV; i += 256) {
            int row = i >> 5, c = (i & 31) * 4;
            int gr = rowTile + row;
            float4 v = make_float4(0.f, 0.f, 0.f, 0.f);
            float scs = 0.f;
            if (gr < N) {
                v = Xv[(size_t)gr * DV + (i & 31)];
                scs = g_sc_s[gr];
            }
            v.x *= scs; v.y *= scs; v.z *= scs; v.w *= scs;
            split_store4(Xh, Xl, row * SB + c, v);
        }
        __syncthreads();

        wmma::fragment<wmma::accumulator, 16, 16, 16, float> acc[4];
#pragma unroll
        for (int nt = 0; nt < 4; nt++) wmma::fill_fragment(acc[nt], 0.0f);

#pragma unroll
        for (int ks = 0; ks < 8; ks++) {
            wmma::fragment<wmma::matrix_a, 16, 16, 16, __nv_bfloat16, wmma::row_major> ah, al;
            wmma::load_matrix_sync(ah, Xh + (wr * 16) * SB + ks * 16, SB);
            wmma::load_matrix_sync(al, Xl + (wr * 16) * SB + ks * 16, SB);
#pragma unroll
            for (int nt = 0; nt < 4; nt++) {
                int col = wc * 64 + nt * 16;
                wmma::fragment<wmma::matrix_b, 16, 16, 16, __nv_bfloat16, wmma::row_major> bh, bl;
                wmma::load_matrix_sync(bh, Wh + (ks * 16) * SB + col, SB);
                wmma::load_matrix_sync(bl, Wl + (ks * 16) * SB + col, SB);
                wmma::mma_sync(acc[nt], ah, bh, acc[nt]);
                wmma::mma_sync(acc[nt], ah, bl, acc[nt]);
                wmma::mma_sync(acc[nt], al, bh, acc[nt]);
            }
        }

        // direct store to g_h (padded, last tile safe)
#pragma unroll
        for (int nt = 0; nt < 4; nt++)
            wmma::store_matrix_sync(
                g_h + (size_t)(rowTile + wr * 16) * D + wc * 64 + nt * 16,
                acc[nt], D, wmma::mem_row_major);
    }

    // ---------------- fill phase (grid-strided), also accumulates wsum ----
    int gid = blockIdx.x * 256 + t;
    int stride = gridDim.x * 256;
    int e = gid;
    for (; e + stride < E; e += 2 * stride) {
        int r0 = receivers[e], r1 = receivers[e + stride];
        int s0 = senders[e],   s1 = senders[e + stride];
        int p0 = atomicAdd(&g_row_cur[r0], 1);
        int p1 = atomicAdd(&g_row_cur[r1], 1);
        g_edge_src[p0] = s0;
        g_edge_src[p1] = s1;
        atomicAdd(&g_wsum[r0], g_sc_s[s0]);
        atomicAdd(&g_wsum[r1], g_sc_s[s1]);
    }
    if (e < E) {
        int r0 = receivers[e], s0 = senders[e];
        int pos = atomicAdd(&g_row_cur[r0], 1);
        g_edge_src[pos] = s0;
        atomicAdd(&g_wsum[r0], g_sc_s[s0]);
    }
}

// ---------------------------------------------------------------------------
// One warp per receiver; plain sums (h prescaled); out = sc_r*(acc + wsum*b).
// 32-bit element indexing (max index N*32 < 2^31).
__global__ __launch_bounds__(256)
void agg_kernel(float* __restrict__ out, const float* __restrict__ bias, int N) {
    int wg = (blockIdx.x * blockDim.x + threadIdx.x) >> 5;
    int lane = threadIdx.x & 31;
    if (wg >= N) return;

    int beg = g_row_start[wg];
    int end = g_row_start[wg + 1];

    const float4* __restrict__ h4 = (const float4*)g_h;
    float4 acc0 = make_float4(0.f, 0.f, 0.f, 0.f);
    float4 acc1 = make_float4(0.f, 0.f, 0.f, 0.f);
    int e = beg;
    for (; e + 7 < end; e += 8) {
        unsigned i0 = ((unsigned)g_edge_src[e]     << 5) + lane;
        unsigned i1 = ((unsigned)g_edge_src[e + 1] << 5) + lane;
        unsigned i2 = ((unsigned)g_edge_src[e + 2] << 5) + lane;
        unsigned i3 = ((unsigned)g_edge_src[e + 3] << 5) + lane;
        unsigned i4 = ((unsigned)g_edge_src[e + 4] << 5) + lane;
        unsigned i5 = ((unsigned)g_edge_src[e + 5] << 5) + lane;
        unsigned i6 = ((unsigned)g_edge_src[e + 6] << 5) + lane;
        unsigned i7 = ((unsigned)g_edge_src[e + 7] << 5) + lane;
        float4 a0 = h4[i0];
        float4 a1 = h4[i1];
        float4 a2 = h4[i2];
        float4 a3 = h4[i3];
        float4 a4 = h4[i4];
        float4 a5 = h4[i5];
        float4 a6 = h4[i6];
        float4 a7 = h4[i7];
        acc0.x += (a0.x + a1.x) + (a2.x + a3.x);
        acc0.y += (a0.y + a1.y) + (a2.y + a3.y);
        acc0.z += (a0.z + a1.z) + (a2.z + a3.z);
        acc0.w += (a0.w + a1.w) + (a2.w + a3.w);
        acc1.x += (a4.x + a5.x) + (a6.x + a7.x);
        acc1.y += (a4.y + a5.y) + (a6.y + a7.y);
        acc1.z += (a4.z + a5.z) + (a6.z + a7.z);
        acc1.w += (a4.w + a5.w) + (a6.w + a7.w);
    }
    for (; e < end; e++) {
        unsigned i0 = ((unsigned)g_edge_src[e] << 5) + lane;
        float4 a0 = h4[i0];
        acc0.x += a0.x; acc0.y += a0.y; acc0.z += a0.z; acc0.w += a0.w;
    }

    float sc = g_sc_r[wg];
    float ws = g_wsum[wg];
    float4 bv = ((const float4*)bias)[lane];
    float4 o;
    o.x = (acc0.x + acc1.x + ws * bv.x) * sc;
    o.y = (acc0.y + acc1.y + ws * bv.y) * sc;
    o.z = (acc0.z + acc1.z + ws * bv.z) * sc;
    o.w = (acc0.w + acc1.w + ws * bv.w) * sc;
    ((float4*)out)[(size_t)wg * DV + lane] = o;
}

// ---------------------------------------------------------------------------
extern "C" void kernel_launch(void* const* d_in, const int* in_sizes, int n_in,
                              void* d_out, int out_size) {
    const float* x         = (const float*)d_in[0];
    const int*   senders   = (const int*)d_in[1];
    const int*   receivers = (const int*)d_in[2];
    const float* W    = (const float*)d_in[n_in - 2];
    const float* bias = (const float*)d_in[n_in - 1];

    int N = in_sizes[0] / D;
    int E = in_sizes[1];

    static bool attr_set = false;
    if (!attr_set) {
        cudaFuncSetAttribute(gemmfill_kernel,
                             cudaFuncAttributeMaxDynamicSharedMemorySize,
                             SMEM_BYTES);
        attr_set = true;
    }

    int nzero = (N + 255) / 256;
    int nSB   = (N + 1023) / 1024;
    int nT    = (N + TM - 1) / TM;
    int nE4   = (E / 4 + 255) / 256 + 1;

    init_kernel   <<<nzero + (D * D) / 256, 256>>>(W, N, nzero);
    degree_kernel <<<nE4, 256>>>(senders, receivers, E);
    scan_kernel   <<<nSB, 1024>>>(N);
    gemmfill_kernel<<<296, 256, SMEM_BYTES>>>(x, senders, receivers, N, E, nT);
    agg_kernel    <<<(N * 32 + 255) / 256, 256>>>((float*)d_out, bias, N);
}

// round 17
// speedup vs baseline: 1.9270x; 1.1524x over previous
#include <cuda_runtime.h>
#include <cuda_bf16.h>
#include <mma.h>
#include <cstdint>

using namespace nvcuda;

// GCN: out = Dr^{-1/2} A Ds^{-1/2} (X W + b)
// init -> degree -> scan(lookback) -> [persistent wmma GEMM + fill(+wsum)] -> gather
// GEMM: B fragments register-resident (loaded once per block from global);
// warp w owns cols [w*16,+16); 64-row X tiles via atomic work-stealing.

#define MAX_N 100000
#define MAX_E 1600000
#define D 128
#define DV 32
#define SB 136            // bf16 smem row stride (elements)
#define TM 64             // rows per tile

#define SMEM_BYTES (2 * TM * SB * 2)   // Xh + Xl = 34816

// ---- device scratch ----
__device__ float g_h[(size_t)(MAX_N + TM) * D];  // prescaled hidden (padded)
__device__ __nv_bfloat16 g_Wh[D * D];            // presplit W hi [k][n]
__device__ __nv_bfloat16 g_Wl[D * D];            // presplit W lo
__device__ float g_sc_s[MAX_N];
__device__ float g_sc_r[MAX_N];
__device__ float g_wsum[MAX_N];
__device__ int   g_deg_s[MAX_N];
__device__ int   g_deg_r[MAX_N];
__device__ int   g_row_start[MAX_N + 1];
__device__ int   g_row_cur[MAX_N];
__device__ int   g_edge_src[MAX_E];
__device__ int   g_tile_ctr;
__device__ unsigned long long g_state[256];      // lookback: (flag<<62)|value

// ---------------------------------------------------------------------------
__global__ void init_kernel(const float* __restrict__ W, int N, int nzero) {
    int t = threadIdx.x;
    int b = blockIdx.x;
    if (b < nzero) {
        int i = b * 256 + t;
        if (i < N) { g_deg_s[i] = 0; g_deg_r[i] = 0; g_wsum[i] = 0.f; }
        if (b == 0) {
            g_state[t] = 0ull;
            if (t == 0) g_tile_ctr = 0;
        }
    } else {
        int idx = (b - nzero) * 256 + t;          // [0, 16384)
        float v = W[idx];
        __nv_bfloat16 h = __float2bfloat16(v);
        g_Wh[idx] = h;
        g_Wl[idx] = __float2bfloat16(v - __bfloat162float(h));
    }
}

__global__ void degree_kernel(const int* __restrict__ senders,
                              const int* __restrict__ receivers, int E) {
    int i = blockIdx.x * blockDim.x + threadIdx.x;
    int e = i * 4;
    if (e + 3 < E) {
        int4 s = *(const int4*)(senders + e);
        int4 r = *(const int4*)(receivers + e);
        atomicAdd(&g_deg_s[s.x], 1); atomicAdd(&g_deg_s[s.y], 1);
        atomicAdd(&g_deg_s[s.z], 1); atomicAdd(&g_deg_s[s.w], 1);
        atomicAdd(&g_deg_r[r.x], 1); atomicAdd(&g_deg_r[r.y], 1);
        atomicAdd(&g_deg_r[r.z], 1); atomicAdd(&g_deg_r[r.w], 1);
    } else {
        for (; e < E; e++) {
            atomicAdd(&g_deg_s[senders[e]], 1);
            atomicAdd(&g_deg_r[receivers[e]], 1);
        }
    }
}

// ---------------------------------------------------------------------------
__global__ __launch_bounds__(1024)
void scan_kernel(int N) {
    __shared__ int s[1024];
    __shared__ int ex_sh;
    int t = threadIdx.x;
    int b = blockIdx.x;
    int i = b * 1024 + t;
    int dr = (i < N) ? g_deg_r[i] : 0;
    s[t] = dr;
    __syncthreads();
    for (int off = 1; off < 1024; off <<= 1) {
        int tmp = (t >= off) ? s[t - off] : 0;
        __syncthreads();
        s[t] += tmp;
        __syncthreads();
    }
    int incl = s[t];
    int total = s[1023];

    if (t == 0) {
        if (b == 0) {
            atomicExch(&g_state[0], (2ull << 62) | (unsigned long long)total);
            ex_sh = 0;
        } else {
            atomicExch(&g_state[b], (1ull << 62) | (unsigned long long)total);
            long long ex = 0;
            int p = b - 1;
            while (true) {
                unsigned long long st;
                do { st = atomicAdd(&g_state[p], 0ull); } while ((st >> 62) == 0);
                ex += (long long)(st & 0x3FFFFFFFFFFFFFFFull);
                if ((st >> 62) == 2ull) break;
                p--;
            }
            atomicExch(&g_state[b],
                       (2ull << 62) | (unsigned long long)(ex + total));
            ex_sh = (int)ex;
        }
    }
    __syncthreads();
    int base = ex_sh;

    if (i < N) {
        int start = base + incl - dr;
        g_row_start[i] = start;
        g_row_cur[i]   = start;
        g_sc_r[i] = rsqrtf((float)max(dr, 1));
        g_sc_s[i] = rsqrtf((float)max(g_deg_s[i], 1));
        if (i == N - 1) g_row_start[N] = base + incl;
    }
}

// ---------------------------------------------------------------------------
// Packed hi/lo split of a float4 -> one 8B store to each of hi/lo.
__device__ __forceinline__ void split_store4(__nv_bfloat16* hi, __nv_bfloat16* lo,
                                             int idx, float4 v) {
    __nv_bfloat162 h01 = __floats2bfloat162_rn(v.x, v.y);
    __nv_bfloat162 h23 = __floats2bfloat162_rn(v.z, v.w);
    float lx = v.x - __bfloat162float(__low2bfloat16(h01));
    float ly = v.y - __bfloat162float(__high2bfloat16(h01));
    float lz = v.z - __bfloat162float(__low2bfloat16(h23));
    float lw = v.w - __bfloat162float(__high2bfloat16(h23));
    __nv_bfloat162 l01 = __floats2bfloat162_rn(lx, ly);
    __nv_bfloat162 l23 = __floats2bfloat162_rn(lz, lw);
    uint2 hp, lp;
    hp.x = *reinterpret_cast<uint32_t*>(&h01);
    hp.y = *reinterpret_cast<uint32_t*>(&h23);
    lp.x = *reinterpret_cast<uint32_t*>(&l01);
    lp.y = *reinterpret_cast<uint32_t*>(&l23);
    *reinterpret_cast<uint2*>(hi + idx) = hp;
    *reinterpret_cast<uint2*>(lo + idx) = lp;
}

// Persistent bf16x3 wmma GEMM: B fragments in registers (one 16-col strip per
// warp, loaded once from global), 64-row X tiles (smem, prescaled by sc_s),
// tile work-stealing, per-mi accumulate + immediate store. Then fill+wsum.
__global__ __launch_bounds__(256, 2)
void gemmfill_kernel(const float* __restrict__ x,
                     const int* __restrict__ senders,
                     const int* __restrict__ receivers,
                     int N, int E, int nT) {
    extern __shared__ char sm[];
    __nv_bfloat16* Xh = (__nv_bfloat16*)sm;
    __nv_bfloat16* Xl = Xh + TM * SB;
    __shared__ int tile_sh;

    int t = threadIdx.x;
    int w = t >> 5;                 // warp owns cols [w*16, w*16+16)

    // load B fragments once per block, straight from global (L2-resident)
    wmma::fragment<wmma::matrix_b, 16, 16, 16, __nv_bfloat16, wmma::row_major> bh[8], bl[8];
#pragma unroll
    for (int ks = 0; ks < 8; ks++) {
        wmma::load_matrix_sync(bh[ks], g_Wh + (ks * 16) * D + w * 16, D);
        wmma::load_matrix_sync(bl[ks], g_Wl + (ks * 16) * D + w * 16, D);
    }

    const float4* Xv = (const float4*)x;

    for (;;) {
        __syncthreads();            // X free from previous mma readers
        if (t == 0) tile_sh = atomicAdd(&g_tile_ctr, 1);
        __syncthreads();            // tile_sh visible
        int tile = tile_sh;
        if (tile >= nT) break;
        int rowTile = tile * TM;

        // stage X tile [TM x 128], rows prescaled by sc_s, packed hi/lo split
        for (int i = t; i < TM * DV; i += 256) {
            int row = i >> 5, c = (i & 31) * 4;
            int gr = rowTile + row;
            float4 v = make_float4(0.f, 0.f, 0.f, 0.f);
            float scs = 0.f;
            if (gr < N) {
                v = Xv[(size_t)gr * DV + (i & 31)];
                scs = g_sc_s[gr];
            }
            v.x *= scs; v.y *= scs; v.z *= scs; v.w *= scs;
            split_store4(Xh, Xl, row * SB + c, v);
        }
        __syncthreads();

        // per 16-row slab: accumulate full K, store immediately
#pragma unroll
        for (int mi = 0; mi < 4; mi++) {
            wmma::fragment<wmma::accumulator, 16, 16, 16, float> acc;
            wmma::fill_fragment(acc, 0.0f);
#pragma unroll
            for (int ks = 0; ks < 8; ks++) {
                wmma::fragment<wmma::matrix_a, 16, 16, 16, __nv_bfloat16, wmma::row_major> ah, al;
                wmma::load_matrix_sync(ah, Xh + (mi * 16) * SB + ks * 16, SB);
                wmma::load_matrix_sync(al, Xl + (mi * 16) * SB + ks * 16, SB);
                wmma::mma_sync(acc, ah, bh[ks], acc);
                wmma::mma_sync(acc, ah, bl[ks], acc);
                wmma::mma_sync(acc, al, bh[ks], acc);
            }
            wmma::store_matrix_sync(
                g_h + (size_t)(rowTile + mi * 16) * D + w * 16,
                acc, D, wmma::mem_row_major);
        }
    }

    // ---------------- fill phase (grid-strided), also accumulates wsum ----
    int gid = blockIdx.x * 256 + t;
    int stride = gridDim.x * 256;
    int e = gid;
    for (; e + stride < E; e += 2 * stride) {
        int r0 = receivers[e], r1 = receivers[e + stride];
        int s0 = senders[e],   s1 = senders[e + stride];
        int p0 = atomicAdd(&g_row_cur[r0], 1);
        int p1 = atomicAdd(&g_row_cur[r1], 1);
        g_edge_src[p0] = s0;
        g_edge_src[p1] = s1;
        atomicAdd(&g_wsum[r0], g_sc_s[s0]);
        atomicAdd(&g_wsum[r1], g_sc_s[s1]);
    }
    if (e < E) {
        int r0 = receivers[e], s0 = senders[e];
        int pos = atomicAdd(&g_row_cur[r0], 1);
        g_edge_src[pos] = s0;
        atomicAdd(&g_wsum[r0], g_sc_s[s0]);
    }
}

// ---------------------------------------------------------------------------
// One warp per receiver; plain sums (h prescaled); out = sc_r*(acc + wsum*b).
__global__ __launch_bounds__(256)
void agg_kernel(float* __restrict__ out, const float* __restrict__ bias, int N) {
    int wg = (blockIdx.x * blockDim.x + threadIdx.x) >> 5;
    int lane = threadIdx.x & 31;
    if (wg >= N) return;

    int beg = g_row_start[wg];
    int end = g_row_start[wg + 1];

    const float4* __restrict__ h4 = (const float4*)g_h;
    float4 acc0 = make_float4(0.f, 0.f, 0.f, 0.f);
    float4 acc1 = make_float4(0.f, 0.f, 0.f, 0.f);
    int e = beg;
    for (; e + 7 < end; e += 8) {
        unsigned i0 = ((unsigned)g_edge_src[e]     << 5) + lane;
        unsigned i1 = ((unsigned)g_edge_src[e + 1] << 5) + lane;
        unsigned i2 = ((unsigned)g_edge_src[e + 2] << 5) + lane;
        unsigned i3 = ((unsigned)g_edge_src[e + 3] << 5) + lane;
        unsigned i4 = ((unsigned)g_edge_src[e + 4] << 5) + lane;
        unsigned i5 = ((unsigned)g_edge_src[e + 5] << 5) + lane;
        unsigned i6 = ((unsigned)g_edge_src[e + 6] << 5) + lane;
        unsigned i7 = ((unsigned)g_edge_src[e + 7] << 5) + lane;
        float4 a0 = h4[i0];
        float4 a1 = h4[i1];
        float4 a2 = h4[i2];
        float4 a3 = h4[i3];
        float4 a4 = h4[i4];
        float4 a5 = h4[i5];
        float4 a6 = h4[i6];
        float4 a7 = h4[i7];
        acc0.x += (a0.x + a1.x) + (a2.x + a3.x);
        acc0.y += (a0.y + a1.y) + (a2.y + a3.y);
        acc0.z += (a0.z + a1.z) + (a2.z + a3.z);
        acc0.w += (a0.w + a1.w) + (a2.w + a3.w);
        acc1.x += (a4.x + a5.x) + (a6.x + a7.x);
        acc1.y += (a4.y + a5.y) + (a6.y + a7.y);
        acc1.z += (a4.z + a5.z) + (a6.z + a7.z);
        acc1.w += (a4.w + a5.w) + (a6.w + a7.w);
    }
    for (; e < end; e++) {
        unsigned i0 = ((unsigned)g_edge_src[e] << 5) + lane;
        float4 a0 = h4[i0];
        acc0.x += a0.x; acc0.y += a0.y; acc0.z += a0.z; acc0.w += a0.w;
    }

    float sc = g_sc_r[wg];
    float ws = g_wsum[wg];
    float4 bv = ((const float4*)bias)[lane];
    float4 o;
    o.x = (acc0.x + acc1.x + ws * bv.x) * sc;
    o.y = (acc0.y + acc1.y + ws * bv.y) * sc;
    o.z = (acc0.z + acc1.z + ws * bv.z) * sc;
    o.w = (acc0.w + acc1.w + ws * bv.w) * sc;
    ((float4*)out)[(size_t)wg * DV + lane] = o;
}

// ---------------------------------------------------------------------------
extern "C" void kernel_launch(void* const* d_in, const int* in_sizes, int n_in,
                              void* d_out, int out_size) {
    const float* x         = (const float*)d_in[0];
    const int*   senders   = (const int*)d_in[1];
    const int*   receivers = (const int*)d_in[2];
    const float* W    = (const float*)d_in[n_in - 2];
    const float* bias = (const float*)d_in[n_in - 1];

    int N = in_sizes[0] / D;
    int E = in_sizes[1];

    static bool attr_set = false;
    if (!attr_set) {
        cudaFuncSetAttribute(gemmfill_kernel,
                             cudaFuncAttributeMaxDynamicSharedMemorySize,
                             SMEM_BYTES);
        attr_set = true;
    }

    int nzero = (N + 255) / 256;
    int nSB   = (N + 1023) / 1024;
    int nT    = (N + TM - 1) / TM;
    int nE4   = (E / 4 + 255) / 256 + 1;

    init_kernel   <<<nzero + (D * D) / 256, 256>>>(W, N, nzero);
    degree_kernel <<<nE4, 256>>>(senders, receivers, E);
    scan_kernel   <<<nSB, 1024>>>(N);
    gemmfill_kernel<<<296, 256, SMEM_BYTES>>>(x, senders, receivers, N, E, nT);
    agg_kernel    <<<(N * 32 + 255) / 256, 256>>>((float*)d_out, bias, N);
}